// round 16
// baseline (speedup 1.0000x reference)
#include <cuda_runtime.h>
#include <cuda_bf16.h>
#include <cuda_fp16.h>
#include <math.h>
#include <cstdint>

#define Dm   768
#define SEQm 512
#define NFS  1024   // B(2) * S(512)
#define LC   103
#define ACLS 119
#define TCLS 11

// ---------------- scratch (static device globals; no allocation) ----------------
__device__ float g_wv1[Dm];         // Wv @ w_dprob
__device__ float g_tbias[Dm];       // Wk @ bq
__device__ float g_cbv;             // bv . w_dprob
__device__ float g_v1[LC*SEQm];     // law_embs . wv1 + cbv
__device__ float g_sc2p[2*LC*8];    // per-tile partial scores2 (8 tiles of 64 rows)
__device__ float g_law0[2*LC];      // cls @ W_law + b_law
__device__ float g_lawfinal[2*LC];
__device__ float g_lawlang[LC*LC];  // laws_table @ W_law + b_law (all candidates)
__device__ __half g_fe16[NFS*Dm];
__device__ __half g_mt16[Dm*Dm];    // MT[j,i] = sum_k Wk[j,k] Wq[i,k]
__device__ __half g_t_f16[NFS*Dm];
__device__ __half g_y_f16[(size_t)LC*SEQm*Dm];

__device__ __forceinline__ float warp_sum(float s){
  #pragma unroll
  for (int o=16;o>0;o>>=1) s += __shfl_xor_sync(0xffffffffu, s, o);
  return s;
}

__device__ __forceinline__ uint32_t smem_u32(const void* p){
  uint32_t a;
  asm("{ .reg .u64 t; cvta.to.shared.u64 t, %1; cvt.u32.u64 %0, t; }" : "=r"(a) : "l"(p));
  return a;
}

__device__ __forceinline__ float ex2f(float x){
  float r;
  asm("ex2.approx.ftz.f32 %0, %1;" : "=f"(r) : "f"(x));
  return r;
}

// ---------------- cp.async helpers ----------------
__device__ __forceinline__ void cp16(uint32_t dst, const void* src){
  asm volatile("cp.async.cg.shared.global [%0], [%1], 16;" :: "r"(dst), "l"(src) : "memory");
}
__device__ __forceinline__ void cp_commit(){ asm volatile("cp.async.commit_group;" ::: "memory"); }
template<int N> __device__ __forceinline__ void cp_wait(){ asm volatile("cp.async.wait_group %0;" :: "n"(N) : "memory"); }

#define LDSM4(r0,r1,r2,r3,addr) \
  asm volatile("ldmatrix.sync.aligned.m8n8.x4.shared.b16 {%0,%1,%2,%3}, [%4];" \
    : "=r"(r0), "=r"(r1), "=r"(r2), "=r"(r3) : "r"(addr))

__device__ __forceinline__ void mma16816(float* c, uint32_t a0, uint32_t a1, uint32_t a2, uint32_t a3,
                                         uint32_t b0, uint32_t b1){
  asm volatile("mma.sync.aligned.m16n8k16.row.col.f32.f16.f16.f32 "
    "{%0,%1,%2,%3}, {%4,%5,%6,%7}, {%8,%9}, {%0,%1,%2,%3};"
    : "+f"(c[0]), "+f"(c[1]), "+f"(c[2]), "+f"(c[3])
    : "r"(a0), "r"(a1), "r"(a2), "r"(a3), "r"(b0), "r"(b1));
}

// shared tile geometry (128-row tiles for GEMMs)
#define TILE_B  16384                 // 128 rows x 128B (64 fp16), SW128-xor swizzled
#define STAGE_B (2*TILE_B)            // 32768 (A tile + B tile)
#define GEMM_SMEM (3*STAGE_B)         // 98304

// one 64-K chunk of 128x128 HMMA work from two swizzled smem tiles
__device__ __forceinline__ void mma_chunk(uint32_t tA, uint32_t tB, float acc[2][8][4],
                                          const uint32_t* cAk, const uint32_t* cBk,
                                          uint32_t rA, uint32_t rB){
  #pragma unroll
  for (int kk=0; kk<4; kk++){
    uint32_t ah[2][4];
    #pragma unroll
    for (int mt=0; mt<2; mt++)
      LDSM4(ah[mt][0],ah[mt][1],ah[mt][2],ah[mt][3], tA + rA + mt*2048 + cAk[kk]);
    #pragma unroll
    for (int p=0; p<4; p++){
      uint32_t b0,b1,b2,b3;
      LDSM4(b0,b1,b2,b3, tB + rB + p*2048 + cBk[kk]);
      #pragma unroll
      for (int mt=0; mt<2; mt++){
        mma16816(acc[mt][2*p],   ah[mt][0],ah[mt][1],ah[mt][2],ah[mt][3], b0, b1);
        mma16816(acc[mt][2*p+1], ah[mt][0],ah[mt][1],ah[mt][2],ah[mt][3], b2, b3);
      }
    }
  }
}

// lane-geometry helper (for the 128x128 GEMM kernels)
struct FragGeo { uint32_t rA, xA, cA0, rB, xB, cB0; int warpM, warpN, lq, lr; };
__device__ __forceinline__ FragGeo frag_geo(int tid){
  FragGeo g;
  int lane = tid & 31, wid = tid >> 5;
  g.warpM = (wid >> 1)*32;
  g.warpN = (wid & 1)*64;
  int rowA = g.warpM + (lane & 15);
  g.rA = (uint32_t)(rowA*128); g.xA = (uint32_t)((rowA & 7) << 4);
  g.cA0 = (uint32_t)(16*(lane >> 4));
  int rowB = g.warpN + 8*((lane >> 4) & 1) + (lane & 7);
  g.rB = (uint32_t)(rowB*128); g.xB = (uint32_t)((rowB & 7) << 4);
  g.cB0 = (uint32_t)(16*((lane >> 3) & 1));
  g.lq = lane & 3; g.lr = lane >> 2;
  return g;
}

// ---------------- generic pipelined HMMA GEMM: C[m,n] = sum_k A[m,k]*B[n,k] (+bias), fp16 out ----------------
#define GK 768
#define GKC 12
__device__ __forceinline__ void gemm_body(const __half* __restrict__ A, const __half* __restrict__ B,
                                          __half* __restrict__ C, const float* __restrict__ bias,
                                          int Ndim, int m0, int n0, char* smem){
  const uint32_t sb = smem_u32(smem);
  const int tid = threadIdx.x;
  FragGeo fg = frag_geo(tid);
  uint32_t cAk[4], cBk[4];
  #pragma unroll
  for (int kk=0;kk<4;kk++){
    cAk[kk] = (fg.cA0 + kk*32) ^ fg.xA;
    cBk[kk] = (fg.cB0 + kk*32) ^ fg.xB;
  }

  const __half* a_f = A + (size_t)m0*GK;
  const __half* b_f = B + (size_t)n0*GK;

  const int cpRow  = tid >> 3;
  const int cpColE = (tid & 7)*8;
  const uint32_t cpColB = (uint32_t)((tid & 7)*16);

  float acc[2][8][4];
  #pragma unroll
  for (int mt=0;mt<2;mt++)
    #pragma unroll
    for (int nt=0;nt<8;nt++)
      #pragma unroll
      for (int q=0;q<4;q++) acc[mt][nt][q]=0.f;

  auto load_chunk = [&](int slot, int k0){
    uint32_t st = sb + slot*STAGE_B;
    #pragma unroll
    for (int i=0;i<4;i++){
      int row = cpRow + i*32;
      uint32_t so = (uint32_t)(row*128) + (cpColB ^ (uint32_t)((row & 7) << 4));
      cp16(st + so,          a_f + (size_t)row*GK + k0 + cpColE);
      cp16(st + TILE_B + so, b_f + (size_t)row*GK + k0 + cpColE);
    }
    cp_commit();
  };

  load_chunk(0, 0);
  load_chunk(1, 64);
  int ldslot = 2, curslot = 0;
  #pragma unroll 1
  for (int kc=0; kc<GKC; kc++){
    if (kc < GKC-1) cp_wait<1>(); else cp_wait<0>();
    __syncthreads();
    if (kc < GKC-2){
      load_chunk(ldslot, (kc+2)*64);
      if (++ldslot == 3) ldslot = 0;
    }
    uint32_t st = sb + curslot*STAGE_B;
    if (++curslot == 3) curslot = 0;
    mma_chunk(st, st + TILE_B, acc, cAk, cBk, fg.rA, fg.rB);
  }

  #pragma unroll
  for (int mt=0; mt<2; mt++)
    #pragma unroll
    for (int nt=0; nt<8; nt++){
      int col = n0 + fg.warpN + nt*8 + 2*fg.lq;
      float b0 = 0.f, b1 = 0.f;
      if (bias){ b0 = bias[col]; b1 = bias[col+1]; }
      #pragma unroll
      for (int g=0; g<2; g++){
        int row = m0 + fg.warpM + mt*16 + g*8 + fg.lr;
        __half2 h = __floats2half2_rn(acc[mt][nt][g*2] + b0, acc[mt][nt][g*2+1] + b1);
        *(__half2*)(C + (size_t)row*Ndim + col) = h;
      }
    }
}

// ---------------- non-pipelined fp32-input HMMA GEMM (for MT inside k1) ----------------
__device__ void mt_body(const float* __restrict__ A32, const float* __restrict__ B32,
                        __half* __restrict__ C, int Ndim, int m0, int n0, char* smem){
  const uint32_t sb = smem_u32(smem);
  const int tid = threadIdx.x;
  FragGeo fg = frag_geo(tid);
  uint32_t cAk[4], cBk[4];
  #pragma unroll
  for (int kk=0;kk<4;kk++){
    cAk[kk] = (fg.cA0 + kk*32) ^ fg.xA;
    cBk[kk] = (fg.cB0 + kk*32) ^ fg.xB;
  }

  float acc[2][8][4];
  #pragma unroll
  for (int mt=0;mt<2;mt++)
    #pragma unroll
    for (int nt=0;nt<8;nt++)
      #pragma unroll
      for (int q=0;q<4;q++) acc[mt][nt][q]=0.f;

  #pragma unroll 1
  for (int kc=0; kc<GKC; kc++){
    __syncthreads();             // previous chunk's LDSM done before overwrite
    #pragma unroll
    for (int i=0;i<8;i++){
      int lin = tid + i*256;
      int row = lin >> 4, c4 = lin & 15;
      uint32_t off = (uint32_t)(row*128 + c4*8);
      off ^= (uint32_t)((row & 7) << 4);
      float4 va = *(const float4*)(A32 + (size_t)(m0+row)*GK + kc*64 + c4*4);
      __half2 h[2] = { __floats2half2_rn(va.x, va.y), __floats2half2_rn(va.z, va.w) };
      *(uint2*)(smem + off) = *(uint2*)h;
      float4 vb = *(const float4*)(B32 + (size_t)(n0+row)*GK + kc*64 + c4*4);
      __half2 g[2] = { __floats2half2_rn(vb.x, vb.y), __floats2half2_rn(vb.z, vb.w) };
      *(uint2*)(smem + TILE_B + off) = *(uint2*)g;
    }
    __syncthreads();
    mma_chunk(sb, sb + TILE_B, acc, cAk, cBk, fg.rA, fg.rB);
  }

  #pragma unroll
  for (int mt=0; mt<2; mt++)
    #pragma unroll
    for (int nt=0; nt<8; nt++){
      int col = n0 + fg.warpN + nt*8 + 2*fg.lq;
      #pragma unroll
      for (int g=0; g<2; g++){
        int row = m0 + fg.warpM + mt*16 + g*8 + fg.lr;
        __half2 h = __floats2half2_rn(acc[mt][nt][g*2], acc[mt][nt][g*2+1]);
        *(__half2*)(C + (size_t)row*Ndim + col) = h;
      }
    }
}

// ---------------- launch 1: MT gemm + prep + fe conv + head-dots + lawlang precompute ----------------
#define CONV_FE  (NFS*Dm/4)           // 196608 float4
#define CONV_BLK 192                  // 192*256*4 = 196608
#define K1_MT   36
#define K1_PREP 193
#define K1_DOTS 59                    // 59*8 = 472 >= 466 warp-dots
#define K1_LL   LC                    // 103 blocks: lawlang precompute

__global__ void __launch_bounds__(256) k1_prep(const float* __restrict__ Wq,
                                               const float* __restrict__ Wk,
                                               const float* __restrict__ fe,
                                               const float* __restrict__ bq,
                                               const float* __restrict__ Wv,
                                               const float* __restrict__ wd,
                                               const float* __restrict__ bv,
                                               const float* __restrict__ output,
                                               const float* __restrict__ laws_table,
                                               const float* __restrict__ W_law,  const float* __restrict__ b_law,
                                               const float* __restrict__ W_accu, const float* __restrict__ b_accu,
                                               const float* __restrict__ W_term, const float* __restrict__ b_term,
                                               float* __restrict__ out){
  __shared__ char smem[2*TILE_B];     // 32 KB, used by MT blocks (and reused by lawlang)
  int lane = threadIdx.x & 31;
  int tid = threadIdx.x;
  if (blockIdx.x < K1_MT){
    mt_body(Wk, Wq, g_mt16, Dm, (blockIdx.x % 6)*128, (blockIdx.x / 6)*128, smem);
  } else if (blockIdx.x < K1_MT + K1_PREP){
    int warp = (blockIdx.x - K1_MT)*8 + (tid >> 5);
    if (warp < Dm){
      const float* row = Wv + (size_t)warp*Dm;
      float s=0.f;
      for (int k=lane;k<Dm;k+=32) s += row[k]*wd[k];
      s = warp_sum(s);
      if (!lane) g_wv1[warp]=s;
    } else if (warp < 2*Dm){
      int n = warp - Dm;
      const float* row = Wk + (size_t)n*Dm;
      float s=0.f;
      for (int k=lane;k<Dm;k+=32) s += row[k]*bq[k];
      s = warp_sum(s);
      if (!lane) g_tbias[n]=s;
    } else if (warp == 2*Dm){
      float s=0.f;
      for (int k=lane;k<Dm;k+=32) s += bv[k]*wd[k];
      s = warp_sum(s);
      if (!lane) g_cbv=s;
    }
  } else if (blockIdx.x < K1_MT + K1_PREP + CONV_BLK){
    int base = (blockIdx.x - K1_MT - K1_PREP)*256 + tid;
    #pragma unroll
    for (int k=0;k<4;k++){
      int i = base + k*(CONV_BLK*256);
      float4 v = ((const float4*)fe)[i];
      ((__half2*)g_fe16)[2*i]   = __floats2half2_rn(v.x, v.y);
      ((__half2*)g_fe16)[2*i+1] = __floats2half2_rn(v.z, v.w);
    }
  } else if (blockIdx.x < K1_MT + K1_PREP + CONV_BLK + K1_DOTS){
    int w = (blockIdx.x - K1_MT - K1_PREP - CONV_BLK)*8 + (tid >> 5);
    if (w < 206){
      int f=w/LC, c=w%LC;
      const float* cls = output + (size_t)f*SEQm*Dm;
      float s=0.f;
      for (int d=lane; d<Dm; d+=32) s += cls[d]*W_law[(size_t)d*LC+c];
      s = warp_sum(s);
      if (!lane) g_law0[w] = s + b_law[c];
    } else if (w < 444){
      int q=w-206; int f=q/ACLS, c=q%ACLS;
      const float* cls = output + (size_t)f*SEQm*Dm;
      float s=0.f;
      for (int d=lane; d<Dm; d+=32) s += cls[d]*W_accu[(size_t)d*ACLS+c];
      s = warp_sum(s);
      if (!lane) out[206+q] = s + b_accu[c];
    } else if (w < 466){
      int q=w-444; int f=q/TCLS, c=q%TCLS;
      const float* cls = output + (size_t)f*SEQm*Dm;
      float s=0.f;
      for (int d=lane; d<Dm; d+=32) s += cls[d]*W_term[(size_t)d*TCLS+c];
      s = warp_sum(s);
      if (!lane) out[444+q] = s + b_term[c];
    }
  } else {
    int no = blockIdx.x - (K1_MT + K1_PREP + CONV_BLK + K1_DOTS);
    float* lb_s = (float*)smem;
    for (int i=tid; i<Dm; i+=256) lb_s[i] = laws_table[(size_t)no*Dm + i];
    __syncthreads();
    if (tid < LC){
      float s = 0.f;
      #pragma unroll 8
      for (int d=0; d<Dm; d++) s += lb_s[d]*W_law[(size_t)d*LC + tid];
      g_lawlang[no*LC + tid] = s + b_law[tid];
    }
  }
}

// ---------------- launch 2: gemmT (48 blocks) + v1y (6592 blocks), concurrent ----------------
__global__ void __launch_bounds__(256,2) k2_t_v1y(const float* __restrict__ y){
  extern __shared__ char smem[];
  if (blockIdx.x < 48){
    gemm_body(g_fe16, g_mt16, g_t_f16, g_tbias, Dm,
              (blockIdx.x & 7)*128, (blockIdx.x >> 3)*128, smem);
  } else {
    int row = (blockIdx.x - 48)*8 + (threadIdx.x >> 5);
    if (row >= LC*SEQm) return;
    int lane = threadIdx.x & 31;
    const float4* p = (const float4*)(y + (size_t)row*Dm);
    __half2* oh = (__half2*)(g_y_f16 + (size_t)row*Dm);
    float s = 0.f;
    #pragma unroll
    for (int k=lane;k<Dm/4;k+=32){
      float4 a = p[k];
      float4 w = *(const float4*)(g_wv1 + 4*k);
      s += a.x*w.x + a.y*w.y + a.z*w.z + a.w*w.w;
      oh[2*k]   = __floats2half2_rn(a.x, a.y);
      oh[2*k+1] = __floats2half2_rn(a.z, a.w);
    }
    s = warp_sum(s);
    if (!lane) g_v1[row] = s + g_cbv;
  }
}

// ---------------- launch 3: attention, M64 tiles, occ 3 (+ scores2 partial) ----------------
#define A2_TILE  8192                 // 64 rows x 128B
#define B2_TILE  16384                // 128 rows x 128B
#define STAGE2_B (A2_TILE + B2_TILE)  // 24576
#define SM2_V1  (2*STAGE2_B)          // 49152, float[512]
#define SM2_MS  (SM2_V1 + 2048)       // float[512] (pre-scaled by log2e)
#define SM2_PS  (SM2_MS + 2048)       // float[2][64]
#define SM2_PA  (SM2_PS + 512)        // float[2][64]
#define SM2_RED (SM2_PA + 512)        // float[2]
#define ATTN_SMEM (SM2_RED + 64)      // 54336

__global__ void __launch_bounds__(256,3)
attn_mma_kernel(const float* __restrict__ mask, const float* __restrict__ bdp,
                const float* __restrict__ wlp){
  extern __shared__ char smem[];
  const uint32_t sb = smem_u32(smem);
  const int tid = threadIdx.x;
  const int lane = tid & 31, wid = tid >> 5;
  const int l = blockIdx.y, m0 = blockIdx.x*64;
  const int warpM = (wid >> 1)*16;     // 4 M-warps x 16 rows
  const int warpN = (wid & 1)*64;      // 2 N-warps x 64 cols

  // A fragment addressing (m16k16, 64-row tile)
  const int rowA = warpM + (lane & 15);
  const uint32_t rA = (uint32_t)(rowA*128), xA = (uint32_t)((rowA & 7) << 4);
  const uint32_t cA0 = (uint32_t)(16*(lane >> 4));
  // B fragment addressing (n64, 128-row tile)
  const int rowB = warpN + 8*((lane >> 4) & 1) + (lane & 7);
  const uint32_t rB = (uint32_t)(rowB*128), xB = (uint32_t)((rowB & 7) << 4);
  const uint32_t cB0 = (uint32_t)(16*((lane >> 3) & 1));
  uint32_t cAk[4], cBk[4];
  #pragma unroll
  for (int kk=0;kk<4;kk++){
    cAk[kk] = (cA0 + kk*32) ^ xA;
    cBk[kk] = (cB0 + kk*32) ^ xB;
  }
  const int lq = lane & 3, lr = lane >> 2;

  float* v1s = (float*)(smem + SM2_V1);
  float* ms  = (float*)(smem + SM2_MS);
  float* ps  = (float*)(smem + SM2_PS);
  float* pa  = (float*)(smem + SM2_PA);
  float* red = (float*)(smem + SM2_RED);

  const __half* yl_f = g_y_f16 + (size_t)l*SEQm*Dm;
  const __half* a_f  = g_t_f16 + (size_t)m0*Dm;

  const int cpRow  = tid >> 3;             // 0..31
  const int cpColE = (tid & 7)*8;
  const uint32_t cpColB = (uint32_t)((tid & 7)*16);

  const float LOG2E = 1.4426950408889634f;
  const float scl2 = 0.03608439182435161f * LOG2E;

  // preload v1 + mask(*log2e)
  {
    v1s[tid]       = g_v1[l*SEQm + tid];
    v1s[tid + 256] = g_v1[l*SEQm + tid + 256];
    ms[tid]        = mask[l*SEQm + tid] * LOG2E;
    ms[tid + 256]  = mask[l*SEQm + tid + 256] * LOG2E;
  }

  float acc[8][4];
  #pragma unroll
  for (int nt=0;nt<8;nt++)
    #pragma unroll
    for (int q=0;q<4;q++) acc[nt][q]=0.f;

  float ssp[2] = {0.f,0.f};   // per-gg (row-group) partial exp-sums
  float aap[2] = {0.f,0.f};

  auto load_chunk = [&](int slot, int k0, int yoff){
    uint32_t st = sb + slot*STAGE2_B;
    #pragma unroll
    for (int i=0;i<2;i++){
      int row = cpRow + i*32;
      uint32_t so = (uint32_t)(row*128) + (cpColB ^ (uint32_t)((row & 7) << 4));
      cp16(st + so, a_f + (size_t)row*Dm + k0 + cpColE);
    }
    #pragma unroll
    for (int i=0;i<4;i++){
      int row = cpRow + i*32;
      uint32_t so = (uint32_t)(row*128) + (cpColB ^ (uint32_t)((row & 7) << 4));
      cp16(st + A2_TILE + so, yl_f + (size_t)row*Dm + yoff + cpColE);
    }
    cp_commit();
  };

  load_chunk(0, 0, 0);
  int pk = 64, pyoff = 64;          // chunk g+1 state
  int ck = 0, en0 = 0;
  #pragma unroll 1
  for (int g=0; g<48; g++){
    cp_wait<0>();
    __syncthreads();
    if (g+1 < 48){
      load_chunk((g+1)&1, pk, pyoff);
      pk += 64; pyoff += 64;
      if (pk == 768){ pk = 0; pyoff += 128*Dm - 768; }
    }
    uint32_t st = sb + (g&1)*STAGE2_B;
    uint32_t tA = st, tB = st + A2_TILE;
    #pragma unroll
    for (int kk=0; kk<4; kk++){
      uint32_t ah0,ah1,ah2,ah3;
      LDSM4(ah0,ah1,ah2,ah3, tA + rA + cAk[kk]);
      #pragma unroll
      for (int p=0; p<4; p++){
        uint32_t b0,b1,b2,b3;
        LDSM4(b0,b1,b2,b3, tB + rB + p*2048 + cBk[kk]);
        mma16816(acc[2*p],   ah0,ah1,ah2,ah3, b0, b1);
        mma16816(acc[2*p+1], ah0,ah1,ah2,ah3, b2, b3);
      }
    }

    if (++ck == 12){
      ck = 0;
      // max-free streaming softmax via ex2 (scl,mask pre-scaled by log2e)
      #pragma unroll
      for (int gg=0; gg<2; gg++){
        float ss = 0.f, aa = 0.f;
        #pragma unroll
        for (int nt=0; nt<8; nt++)
          #pragma unroll
          for (int p=0; p<2; p++){
            int c = en0 + warpN + nt*8 + 2*lq + p;
            float e = ex2f(fmaf(acc[nt][gg*2+p], scl2, ms[c]));
            ss += e; aa += e*v1s[c];
          }
        ssp[gg] += ss;
        aap[gg] += aa;
      }
      en0 += 128;
      #pragma unroll
      for (int nt=0;nt<8;nt++)
        #pragma unroll
        for (int q=0;q<4;q++) acc[nt][q]=0.f;
    }
  }

  // final combine
  #pragma unroll
  for (int gg=0; gg<2; gg++){
    float ss = ssp[gg], aa = aap[gg];
    ss += __shfl_xor_sync(0xffffffffu, ss, 1);
    ss += __shfl_xor_sync(0xffffffffu, ss, 2);
    aa += __shfl_xor_sync(0xffffffffu, aa, 1);
    aa += __shfl_xor_sync(0xffffffffu, aa, 2);
    if (lq == 0){
      int row = warpM + gg*8 + lr;       // 0..63
      int h = wid & 1;
      ps[h*64+row]=ss; pa[h*64+row]=aa;
    }
  }
  __syncthreads();
  // fused scores2 partial over this 64-row tile
  if (tid < 64){
    int fs = m0 + tid;
    float val = (pa[tid] + pa[64+tid]) / (ps[tid] + ps[64+tid]) + bdp[0];
    float part = val * wlp[fs & 511];
    part = warp_sum(part);
    if ((tid & 31) == 0) red[tid >> 5] = part;
  }
  __syncthreads();
  if (tid == 0){
    int f = m0 >> 9;
    g_sc2p[((f*LC + l) << 3) | (blockIdx.x & 7)] = red[0]+red[1];
  }
}

// ---------------- launch 4: head1 (warp-per-output law combine) ----------------
__global__ void __launch_bounds__(256) head1_kernel(const float* __restrict__ blp,
                             const float* __restrict__ W_rule, const float* __restrict__ b_rule,
                             const float* __restrict__ W_fact, const float* __restrict__ b_fact,
                             float* __restrict__ out){
  int w = blockIdx.x*8 + (threadIdx.x >> 5);
  int lane = threadIdx.x & 31;
  if (w >= 2*LC) return;
  int f = w/LC, c = w%LC;
  float b0 = blp[0];
  float s = 0.f;
  for (int j=lane; j<LC; j+=32){
    const float* p = g_sc2p + ((f*LC + j) << 3);
    float sc2 = ((p[0]+p[1])+(p[2]+p[3])) + ((p[4]+p[5])+(p[6]+p[7])) + b0;
    s += g_law0[f*LC+j]*W_rule[(size_t)j*LC+c] + sc2*W_fact[(size_t)j*LC+c];
  }
  s = warp_sum(s);
  if (!lane){
    s += b_rule[c] + b_fact[c];
    g_lawfinal[w] = s;
    out[w] = s;
  }
}

// ---------------- launch 5: head2 (argmax + lawlang gather), one block ----------------
__global__ void __launch_bounds__(256) head2_kernel(float* __restrict__ out){
  __shared__ int no_s[2];
  int tid = threadIdx.x, wid = tid >> 5, lane = tid & 31;
  if (wid < 2){
    int f = wid;
    float bv = -3.4e38f; int bi = 0;
    for (int c=lane; c<LC; c+=32){
      float v = g_lawfinal[f*LC + c];
      if (v > bv){ bv = v; bi = c; }
    }
    #pragma unroll
    for (int o=16;o>0;o>>=1){
      float ov = __shfl_xor_sync(0xffffffffu, bv, o);
      int   oi = __shfl_xor_sync(0xffffffffu, bi, o);
      if (ov > bv || (ov == bv && oi < bi)){ bv = ov; bi = oi; }
    }
    if (!lane){
      no_s[f] = bi;
      out[672 + f] = (float)bi;
    }
  }
  __syncthreads();
  for (int i=tid; i<2*LC; i+=256){
    int f = i/LC, c = i%LC;
    out[466 + i] = g_lawlang[no_s[f]*LC + c];
  }
}

// ---------------- launch ----------------
extern "C" void kernel_launch(void* const* d_in, const int* in_sizes, int n_in,
                              void* d_out, int out_size){
  const float* output     = (const float*)d_in[0];
  const float* fact_emb   = (const float*)d_in[1];
  const float* law_embs   = (const float*)d_in[2];
  const float* law_masks  = (const float*)d_in[3];
  const float* laws_table = (const float*)d_in[4];
  const float* Wq  = (const float*)d_in[5];
  const float* bq  = (const float*)d_in[6];
  const float* Wk  = (const float*)d_in[7];
  // d_in[8] = bk : softmax-invariant, drops out
  const float* Wv  = (const float*)d_in[9];
  const float* bv  = (const float*)d_in[10];
  const float* w_dprob   = (const float*)d_in[11];
  const float* b_dprob   = (const float*)d_in[12];
  const float* w_lawprob = (const float*)d_in[13];
  const float* b_lawprob = (const float*)d_in[14];
  const float* W_rulelaw = (const float*)d_in[15];
  const float* b_rulelaw = (const float*)d_in[16];
  const float* W_factlaw = (const float*)d_in[17];
  const float* b_factlaw = (const float*)d_in[18];
  const float* W_law = (const float*)d_in[19];
  const float* b_law = (const float*)d_in[20];
  const float* W_accu = (const float*)d_in[21];
  const float* b_accu = (const float*)d_in[22];
  const float* W_term = (const float*)d_in[23];
  const float* b_term = (const float*)d_in[24];
  float* out = (float*)d_out;

  cudaFuncSetAttribute(attn_mma_kernel, cudaFuncAttributeMaxDynamicSharedMemorySize, ATTN_SMEM);
  cudaFuncSetAttribute(k2_t_v1y, cudaFuncAttributeMaxDynamicSharedMemorySize, GEMM_SMEM);

  k1_prep<<<K1_MT + K1_PREP + CONV_BLK + K1_DOTS + K1_LL, 256>>>(
      Wq, Wk, fact_emb, bq, Wv, w_dprob, bv,
      output, laws_table, W_law, b_law, W_accu, b_accu, W_term, b_term, out);
  k2_t_v1y<<<48 + 6592, 256, GEMM_SMEM>>>(law_embs);
  attn_mma_kernel<<<dim3(NFS/64, LC), 256, ATTN_SMEM>>>(law_masks, b_dprob, w_lawprob);
  head1_kernel<<<26,256>>>(b_lawprob, W_rulelaw, b_rulelaw, W_factlaw, b_factlaw, out);
  head2_kernel<<<1,256>>>(out);
}

// round 17
// speedup vs baseline: 1.1288x; 1.1288x over previous
#include <cuda_runtime.h>
#include <cuda_bf16.h>
#include <cuda_fp16.h>
#include <math.h>
#include <cstdint>

#define Dm   768
#define SEQm 512
#define NFS  1024   // B(2) * S(512)
#define LC   103
#define ACLS 119
#define TCLS 11

// ---------------- scratch (static device globals; no allocation) ----------------
__device__ float g_wv1[Dm];         // Wv @ w_dprob
__device__ float g_tbias[Dm];       // Wk @ bq
__device__ float g_cbv;             // bv . w_dprob
__device__ float g_v1[LC*SEQm];     // law_embs . wv1 + cbv
__device__ float g_sc2p[2*LC*4];    // per-tile partial scores2
__device__ float g_law0[2*LC];      // cls @ W_law + b_law
__device__ float g_lawfinal[2*LC];
__device__ float g_lawlang[LC*LC];  // laws_table @ W_law + b_law (all candidates)
__device__ __half g_fe16[NFS*Dm];
__device__ __half g_mt16[Dm*Dm];    // MT[j,i] = sum_k Wk[j,k] Wq[i,k]
__device__ __half g_t_f16[NFS*Dm];
__device__ __half g_y_f16[(size_t)LC*SEQm*Dm];

__device__ __forceinline__ float warp_sum(float s){
  #pragma unroll
  for (int o=16;o>0;o>>=1) s += __shfl_xor_sync(0xffffffffu, s, o);
  return s;
}

__device__ __forceinline__ uint32_t smem_u32(const void* p){
  uint32_t a;
  asm("{ .reg .u64 t; cvta.to.shared.u64 t, %1; cvt.u32.u64 %0, t; }" : "=r"(a) : "l"(p));
  return a;
}

__device__ __forceinline__ float ex2f(float x){
  float r;
  asm("ex2.approx.ftz.f32 %0, %1;" : "=f"(r) : "f"(x));
  return r;
}

// ---------------- cp.async helpers ----------------
__device__ __forceinline__ void cp16(uint32_t dst, const void* src){
  asm volatile("cp.async.cg.shared.global [%0], [%1], 16;" :: "r"(dst), "l"(src) : "memory");
}
__device__ __forceinline__ void cp_commit(){ asm volatile("cp.async.commit_group;" ::: "memory"); }
template<int N> __device__ __forceinline__ void cp_wait(){ asm volatile("cp.async.wait_group %0;" :: "n"(N) : "memory"); }

#define LDSM4(r0,r1,r2,r3,addr) \
  asm volatile("ldmatrix.sync.aligned.m8n8.x4.shared.b16 {%0,%1,%2,%3}, [%4];" \
    : "=r"(r0), "=r"(r1), "=r"(r2), "=r"(r3) : "r"(addr))

__device__ __forceinline__ void mma16816(float* c, uint32_t a0, uint32_t a1, uint32_t a2, uint32_t a3,
                                         uint32_t b0, uint32_t b1){
  asm volatile("mma.sync.aligned.m16n8k16.row.col.f32.f16.f16.f32 "
    "{%0,%1,%2,%3}, {%4,%5,%6,%7}, {%8,%9}, {%0,%1,%2,%3};"
    : "+f"(c[0]), "+f"(c[1]), "+f"(c[2]), "+f"(c[3])
    : "r"(a0), "r"(a1), "r"(a2), "r"(a3), "r"(b0), "r"(b1));
}

// shared tile geometry
#define TILE_B  16384                 // 128 rows x 128B (64 fp16), SW128-xor swizzled
#define STAGE_B (2*TILE_B)            // 32768 (A tile + B tile)
#define GEMM_SMEM (3*STAGE_B)         // 98304

// one 64-K chunk of 128x128 HMMA work from two swizzled smem tiles
__device__ __forceinline__ void mma_chunk(uint32_t tA, uint32_t tB, float acc[2][8][4],
                                          const uint32_t* cAk, const uint32_t* cBk,
                                          uint32_t rA, uint32_t rB){
  #pragma unroll
  for (int kk=0; kk<4; kk++){
    uint32_t ah[2][4];
    #pragma unroll
    for (int mt=0; mt<2; mt++)
      LDSM4(ah[mt][0],ah[mt][1],ah[mt][2],ah[mt][3], tA + rA + mt*2048 + cAk[kk]);
    #pragma unroll
    for (int p=0; p<4; p++){
      uint32_t b0,b1,b2,b3;
      LDSM4(b0,b1,b2,b3, tB + rB + p*2048 + cBk[kk]);
      #pragma unroll
      for (int mt=0; mt<2; mt++){
        mma16816(acc[mt][2*p],   ah[mt][0],ah[mt][1],ah[mt][2],ah[mt][3], b0, b1);
        mma16816(acc[mt][2*p+1], ah[mt][0],ah[mt][1],ah[mt][2],ah[mt][3], b2, b3);
      }
    }
  }
}

// lane-geometry helper (shared by all HMMA kernels)
struct FragGeo { uint32_t rA, xA, cA0, rB, xB, cB0; int warpM, warpN, lq, lr; };
__device__ __forceinline__ FragGeo frag_geo(int tid){
  FragGeo g;
  int lane = tid & 31, wid = tid >> 5;
  g.warpM = (wid >> 1)*32;
  g.warpN = (wid & 1)*64;
  int rowA = g.warpM + (lane & 15);
  g.rA = (uint32_t)(rowA*128); g.xA = (uint32_t)((rowA & 7) << 4);
  g.cA0 = (uint32_t)(16*(lane >> 4));
  int rowB = g.warpN + 8*((lane >> 4) & 1) + (lane & 7);
  g.rB = (uint32_t)(rowB*128); g.xB = (uint32_t)((rowB & 7) << 4);
  g.cB0 = (uint32_t)(16*((lane >> 3) & 1));
  g.lq = lane & 3; g.lr = lane >> 2;
  return g;
}

// ---------------- generic pipelined HMMA GEMM: C[m,n] = sum_k A[m,k]*B[n,k] (+bias), fp16 out ----------------
#define GK 768
#define GKC 12
__device__ __forceinline__ void gemm_body(const __half* __restrict__ A, const __half* __restrict__ B,
                                          __half* __restrict__ C, const float* __restrict__ bias,
                                          int Ndim, int m0, int n0, char* smem){
  const uint32_t sb = smem_u32(smem);
  const int tid = threadIdx.x;
  FragGeo fg = frag_geo(tid);
  uint32_t cAk[4], cBk[4];
  #pragma unroll
  for (int kk=0;kk<4;kk++){
    cAk[kk] = (fg.cA0 + kk*32) ^ fg.xA;
    cBk[kk] = (fg.cB0 + kk*32) ^ fg.xB;
  }

  const __half* a_f = A + (size_t)m0*GK;
  const __half* b_f = B + (size_t)n0*GK;

  const int cpRow  = tid >> 3;
  const int cpColE = (tid & 7)*8;
  const uint32_t cpColB = (uint32_t)((tid & 7)*16);

  float acc[2][8][4];
  #pragma unroll
  for (int mt=0;mt<2;mt++)
    #pragma unroll
    for (int nt=0;nt<8;nt++)
      #pragma unroll
      for (int q=0;q<4;q++) acc[mt][nt][q]=0.f;

  auto load_chunk = [&](int slot, int k0){
    uint32_t st = sb + slot*STAGE_B;
    #pragma unroll
    for (int i=0;i<4;i++){
      int row = cpRow + i*32;
      uint32_t so = (uint32_t)(row*128) + (cpColB ^ (uint32_t)((row & 7) << 4));
      cp16(st + so,          a_f + (size_t)row*GK + k0 + cpColE);
      cp16(st + TILE_B + so, b_f + (size_t)row*GK + k0 + cpColE);
    }
    cp_commit();
  };

  load_chunk(0, 0);
  load_chunk(1, 64);
  int ldslot = 2, curslot = 0;
  #pragma unroll 1
  for (int kc=0; kc<GKC; kc++){
    if (kc < GKC-1) cp_wait<1>(); else cp_wait<0>();
    __syncthreads();
    if (kc < GKC-2){
      load_chunk(ldslot, (kc+2)*64);
      if (++ldslot == 3) ldslot = 0;
    }
    uint32_t st = sb + curslot*STAGE_B;
    if (++curslot == 3) curslot = 0;
    mma_chunk(st, st + TILE_B, acc, cAk, cBk, fg.rA, fg.rB);
  }

  #pragma unroll
  for (int mt=0; mt<2; mt++)
    #pragma unroll
    for (int nt=0; nt<8; nt++){
      int col = n0 + fg.warpN + nt*8 + 2*fg.lq;
      float b0 = 0.f, b1 = 0.f;
      if (bias){ b0 = bias[col]; b1 = bias[col+1]; }
      #pragma unroll
      for (int g=0; g<2; g++){
        int row = m0 + fg.warpM + mt*16 + g*8 + fg.lr;
        __half2 h = __floats2half2_rn(acc[mt][nt][g*2] + b0, acc[mt][nt][g*2+1] + b1);
        *(__half2*)(C + (size_t)row*Ndim + col) = h;
      }
    }
}

// ---------------- non-pipelined fp32-input HMMA GEMM (for MT inside k1) ----------------
__device__ void mt_body(const float* __restrict__ A32, const float* __restrict__ B32,
                        __half* __restrict__ C, int Ndim, int m0, int n0, char* smem){
  const uint32_t sb = smem_u32(smem);
  const int tid = threadIdx.x;
  FragGeo fg = frag_geo(tid);
  uint32_t cAk[4], cBk[4];
  #pragma unroll
  for (int kk=0;kk<4;kk++){
    cAk[kk] = (fg.cA0 + kk*32) ^ fg.xA;
    cBk[kk] = (fg.cB0 + kk*32) ^ fg.xB;
  }

  float acc[2][8][4];
  #pragma unroll
  for (int mt=0;mt<2;mt++)
    #pragma unroll
    for (int nt=0;nt<8;nt++)
      #pragma unroll
      for (int q=0;q<4;q++) acc[mt][nt][q]=0.f;

  #pragma unroll 1
  for (int kc=0; kc<GKC; kc++){
    __syncthreads();             // previous chunk's LDSM done before overwrite
    #pragma unroll
    for (int i=0;i<8;i++){
      int lin = tid + i*256;
      int row = lin >> 4, c4 = lin & 15;
      uint32_t off = (uint32_t)(row*128 + c4*8);
      off ^= (uint32_t)((row & 7) << 4);
      float4 va = *(const float4*)(A32 + (size_t)(m0+row)*GK + kc*64 + c4*4);
      __half2 h[2] = { __floats2half2_rn(va.x, va.y), __floats2half2_rn(va.z, va.w) };
      *(uint2*)(smem + off) = *(uint2*)h;
      float4 vb = *(const float4*)(B32 + (size_t)(n0+row)*GK + kc*64 + c4*4);
      __half2 g[2] = { __floats2half2_rn(vb.x, vb.y), __floats2half2_rn(vb.z, vb.w) };
      *(uint2*)(smem + TILE_B + off) = *(uint2*)g;
    }
    __syncthreads();
    mma_chunk(sb, sb + TILE_B, acc, cAk, cBk, fg.rA, fg.rB);
  }

  #pragma unroll
  for (int mt=0; mt<2; mt++)
    #pragma unroll
    for (int nt=0; nt<8; nt++){
      int col = n0 + fg.warpN + nt*8 + 2*fg.lq;
      #pragma unroll
      for (int g=0; g<2; g++){
        int row = m0 + fg.warpM + mt*16 + g*8 + fg.lr;
        __half2 h = __floats2half2_rn(acc[mt][nt][g*2], acc[mt][nt][g*2+1]);
        *(__half2*)(C + (size_t)row*Ndim + col) = h;
      }
    }
}

// ---------------- launch 1: MT gemm + prep + fe conv + head-dots + lawlang precompute ----------------
#define CONV_FE  (NFS*Dm/4)           // 196608 float4
#define CONV_BLK 192                  // 192*256*4 = 196608
#define K1_MT   36
#define K1_PREP 193
#define K1_DOTS 59                    // 59*8 = 472 >= 466 warp-dots
#define K1_LL   LC                    // 103 blocks: lawlang precompute

__global__ void __launch_bounds__(256) k1_prep(const float* __restrict__ Wq,
                                               const float* __restrict__ Wk,
                                               const float* __restrict__ fe,
                                               const float* __restrict__ bq,
                                               const float* __restrict__ Wv,
                                               const float* __restrict__ wd,
                                               const float* __restrict__ bv,
                                               const float* __restrict__ output,
                                               const float* __restrict__ laws_table,
                                               const float* __restrict__ W_law,  const float* __restrict__ b_law,
                                               const float* __restrict__ W_accu, const float* __restrict__ b_accu,
                                               const float* __restrict__ W_term, const float* __restrict__ b_term,
                                               float* __restrict__ out){
  __shared__ char smem[2*TILE_B];     // 32 KB, used by MT blocks (and reused by lawlang)
  int lane = threadIdx.x & 31;
  int tid = threadIdx.x;
  if (blockIdx.x < K1_MT){
    mt_body(Wk, Wq, g_mt16, Dm, (blockIdx.x % 6)*128, (blockIdx.x / 6)*128, smem);
  } else if (blockIdx.x < K1_MT + K1_PREP){
    int warp = (blockIdx.x - K1_MT)*8 + (tid >> 5);
    if (warp < Dm){
      const float* row = Wv + (size_t)warp*Dm;
      float s=0.f;
      for (int k=lane;k<Dm;k+=32) s += row[k]*wd[k];
      s = warp_sum(s);
      if (!lane) g_wv1[warp]=s;
    } else if (warp < 2*Dm){
      int n = warp - Dm;
      const float* row = Wk + (size_t)n*Dm;
      float s=0.f;
      for (int k=lane;k<Dm;k+=32) s += row[k]*bq[k];
      s = warp_sum(s);
      if (!lane) g_tbias[n]=s;
    } else if (warp == 2*Dm){
      float s=0.f;
      for (int k=lane;k<Dm;k+=32) s += bv[k]*wd[k];
      s = warp_sum(s);
      if (!lane) g_cbv=s;
    }
  } else if (blockIdx.x < K1_MT + K1_PREP + CONV_BLK){
    int base = (blockIdx.x - K1_MT - K1_PREP)*256 + tid;
    #pragma unroll
    for (int k=0;k<4;k++){
      int i = base + k*(CONV_BLK*256);
      float4 v = ((const float4*)fe)[i];
      ((__half2*)g_fe16)[2*i]   = __floats2half2_rn(v.x, v.y);
      ((__half2*)g_fe16)[2*i+1] = __floats2half2_rn(v.z, v.w);
    }
  } else if (blockIdx.x < K1_MT + K1_PREP + CONV_BLK + K1_DOTS){
    int w = (blockIdx.x - K1_MT - K1_PREP - CONV_BLK)*8 + (tid >> 5);
    if (w < 206){
      int f=w/LC, c=w%LC;
      const float* cls = output + (size_t)f*SEQm*Dm;
      float s=0.f;
      for (int d=lane; d<Dm; d+=32) s += cls[d]*W_law[(size_t)d*LC+c];
      s = warp_sum(s);
      if (!lane) g_law0[w] = s + b_law[c];
    } else if (w < 444){
      int q=w-206; int f=q/ACLS, c=q%ACLS;
      const float* cls = output + (size_t)f*SEQm*Dm;
      float s=0.f;
      for (int d=lane; d<Dm; d+=32) s += cls[d]*W_accu[(size_t)d*ACLS+c];
      s = warp_sum(s);
      if (!lane) out[206+q] = s + b_accu[c];
    } else if (w < 466){
      int q=w-444; int f=q/TCLS, c=q%TCLS;
      const float* cls = output + (size_t)f*SEQm*Dm;
      float s=0.f;
      for (int d=lane; d<Dm; d+=32) s += cls[d]*W_term[(size_t)d*TCLS+c];
      s = warp_sum(s);
      if (!lane) out[444+q] = s + b_term[c];
    }
  } else {
    int no = blockIdx.x - (K1_MT + K1_PREP + CONV_BLK + K1_DOTS);
    float* lb_s = (float*)smem;
    for (int i=tid; i<Dm; i+=256) lb_s[i] = laws_table[(size_t)no*Dm + i];
    __syncthreads();
    if (tid < LC){
      float s = 0.f;
      #pragma unroll 8
      for (int d=0; d<Dm; d++) s += lb_s[d]*W_law[(size_t)d*LC + tid];
      g_lawlang[no*LC + tid] = s + b_law[tid];
    }
  }
}

// ---------------- launch 2: gemmT (48 blocks) + v1y (6592 blocks), concurrent ----------------
__global__ void __launch_bounds__(256,2) k2_t_v1y(const float* __restrict__ y){
  extern __shared__ char smem[];
  if (blockIdx.x < 48){
    gemm_body(g_fe16, g_mt16, g_t_f16, g_tbias, Dm,
              (blockIdx.x & 7)*128, (blockIdx.x >> 3)*128, smem);
  } else {
    int row = (blockIdx.x - 48)*8 + (threadIdx.x >> 5);
    if (row >= LC*SEQm) return;
    int lane = threadIdx.x & 31;
    const float4* p = (const float4*)(y + (size_t)row*Dm);
    __half2* oh = (__half2*)(g_y_f16 + (size_t)row*Dm);
    float s = 0.f;
    #pragma unroll
    for (int k=lane;k<Dm/4;k+=32){
      float4 a = p[k];
      float4 w = *(const float4*)(g_wv1 + 4*k);
      s += a.x*w.x + a.y*w.y + a.z*w.z + a.w*w.w;
      oh[2*k]   = __floats2half2_rn(a.x, a.y);
      oh[2*k+1] = __floats2half2_rn(a.z, a.w);
    }
    s = warp_sum(s);
    if (!lane) g_v1[row] = s + g_cbv;
  }
}

// ---------------- launch 3: fused attention (M128, 3-stage, occ 2, ex2 softmax) ----------------
#define SM_V1   (3*STAGE_B)           // 98304, float[512]
#define SM_MS   (SM_V1 + 2048)        // float[512] (pre-scaled by log2e)
#define SM_PS   (SM_MS + 2048)        // float[2][128]
#define SM_PA   (SM_PS + 1024)        // float[2][128]
#define SM_RED  (SM_PA + 1024)        // float[4]
#define ATTN_SMEM (SM_RED + 128)      // 104576

__global__ void __launch_bounds__(256,2)
attn_mma_kernel(const float* __restrict__ mask, const float* __restrict__ bdp,
                const float* __restrict__ wlp){
  extern __shared__ char smem[];
  const uint32_t sb = smem_u32(smem);
  const int tid = threadIdx.x;
  const int wid = tid >> 5;
  const int l = blockIdx.y, m0 = blockIdx.x*128;
  FragGeo fg = frag_geo(tid);
  uint32_t cAk[4], cBk[4];
  #pragma unroll
  for (int kk=0;kk<4;kk++){
    cAk[kk] = (fg.cA0 + kk*32) ^ fg.xA;
    cBk[kk] = (fg.cB0 + kk*32) ^ fg.xB;
  }

  float* v1s = (float*)(smem + SM_V1);
  float* ms  = (float*)(smem + SM_MS);
  float* ps  = (float*)(smem + SM_PS);
  float* pa  = (float*)(smem + SM_PA);
  float* red = (float*)(smem + SM_RED);

  const __half* yl_f = g_y_f16 + (size_t)l*SEQm*Dm;
  const __half* a_f  = g_t_f16 + (size_t)m0*Dm;

  const int cpRow  = tid >> 3;
  const int cpColE = (tid & 7)*8;
  const uint32_t cpColB = (uint32_t)((tid & 7)*16);

  const float LOG2E = 1.4426950408889634f;
  const float scl2 = 0.03608439182435161f * LOG2E;   // (1/sqrt(768))*log2e

  // preload all 512 v1 + mask(*log2e)
  {
    v1s[tid]       = g_v1[l*SEQm + tid];
    v1s[tid + 256] = g_v1[l*SEQm + tid + 256];
    ms[tid]        = mask[l*SEQm + tid] * LOG2E;
    ms[tid + 256]  = mask[l*SEQm + tid + 256] * LOG2E;
  }

  float acc[2][8][4];
  #pragma unroll
  for (int mt=0;mt<2;mt++)
    #pragma unroll
    for (int nt=0;nt<8;nt++)
      #pragma unroll
      for (int q=0;q<4;q++) acc[mt][nt][q]=0.f;

  float ssp[2][2] = {{0.f,0.f},{0.f,0.f}};
  float aap[2][2] = {{0.f,0.f},{0.f,0.f}};

  auto load_chunk = [&](int slot, int k0, int yoff){
    uint32_t st = sb + slot*STAGE_B;
    #pragma unroll
    for (int i=0;i<4;i++){
      int row = cpRow + i*32;
      uint32_t so = (uint32_t)(row*128) + (cpColB ^ (uint32_t)((row & 7) << 4));
      cp16(st + so,          a_f  + (size_t)row*Dm + k0 + cpColE);
      cp16(st + TILE_B + so, yl_f + (size_t)row*Dm + yoff + cpColE);
    }
    cp_commit();
  };

  load_chunk(0, 0, 0);
  load_chunk(1, 64, 64);
  int ldslot = 2, curslot = 0;
  int pk = 128, pyoff = 128;        // prefetch chunk-index state (chunk g+2)
  int ck = 0, en0 = 0;              // compute-side counters
  const int lq = fg.lq;
  #pragma unroll 1
  for (int g=0; g<48; g++){
    if (g < 47) cp_wait<1>(); else cp_wait<0>();
    __syncthreads();
    if (g+2 < 48){
      load_chunk(ldslot, pk, pyoff);
      if (++ldslot == 3) ldslot = 0;
      pk += 64; pyoff += 64;
      if (pk == 768){ pk = 0; pyoff += 128*Dm - 768; }
    }
    uint32_t st = sb + curslot*STAGE_B;
    if (++curslot == 3) curslot = 0;
    mma_chunk(st, st + TILE_B, acc, cAk, cBk, fg.rA, fg.rB);

    if (++ck == 12){
      ck = 0;
      // max-free streaming softmax via ex2 (scale+mask pre-multiplied by log2e)
      #pragma unroll
      for (int mt=0; mt<2; mt++)
        #pragma unroll
        for (int gg=0; gg<2; gg++){
          float ss = 0.f, aa = 0.f;
          #pragma unroll
          for (int nt=0; nt<8; nt++)
            #pragma unroll
            for (int p=0; p<2; p++){
              int c = en0 + fg.warpN + nt*8 + 2*lq + p;
              float e = ex2f(fmaf(acc[mt][nt][gg*2+p], scl2, ms[c]));
              ss += e; aa += e*v1s[c];
            }
          ssp[mt][gg] += ss;
          aap[mt][gg] += aa;
        }
      en0 += 128;
      #pragma unroll
      for (int mt=0;mt<2;mt++)
        #pragma unroll
        for (int nt=0;nt<8;nt++)
          #pragma unroll
          for (int q=0;q<4;q++) acc[mt][nt][q]=0.f;
    }
  }

  // single final combine
  {
    #pragma unroll
    for (int mt=0; mt<2; mt++)
      #pragma unroll
      for (int gg=0; gg<2; gg++){
        float ss = ssp[mt][gg], aa = aap[mt][gg];
        ss += __shfl_xor_sync(0xffffffffu, ss, 1);
        ss += __shfl_xor_sync(0xffffffffu, ss, 2);
        aa += __shfl_xor_sync(0xffffffffu, aa, 1);
        aa += __shfl_xor_sync(0xffffffffu, aa, 2);
        if (lq == 0){
          int row = fg.warpM + mt*16 + gg*8 + fg.lr;
          int h = wid & 1;
          ps[h*128+row]=ss; pa[h*128+row]=aa;
        }
      }
  }
  __syncthreads();
  // fused scores2 partial: sum_{si in tile} laws2[f,l,si]*wlp[si]
  if (tid < 128){
    int fs = m0 + tid;
    float val = (pa[tid] + pa[128+tid]) / (ps[tid] + ps[128+tid]) + bdp[0];
    float part = val * wlp[fs & 511];
    part = warp_sum(part);
    if ((tid & 31) == 0) red[tid >> 5] = part;
  }
  __syncthreads();
  if (tid == 0){
    int f = m0 >> 9;
    g_sc2p[((f*LC + l) << 2) | (blockIdx.x & 3)] = red[0]+red[1]+red[2]+red[3];
  }
}

// ---------------- launch 4: head1 (warp-per-output law combine) ----------------
__global__ void __launch_bounds__(256) head1_kernel(const float* __restrict__ blp,
                             const float* __restrict__ W_rule, const float* __restrict__ b_rule,
                             const float* __restrict__ W_fact, const float* __restrict__ b_fact,
                             float* __restrict__ out){
  int w = blockIdx.x*8 + (threadIdx.x >> 5);
  int lane = threadIdx.x & 31;
  if (w >= 2*LC) return;
  int f = w/LC, c = w%LC;
  float b0 = blp[0];
  float s = 0.f;
  for (int j=lane; j<LC; j+=32){
    const float* p = g_sc2p + ((f*LC + j) << 2);
    float sc2 = p[0]+p[1]+p[2]+p[3] + b0;
    s += g_law0[f*LC+j]*W_rule[(size_t)j*LC+c] + sc2*W_fact[(size_t)j*LC+c];
  }
  s = warp_sum(s);
  if (!lane){
    s += b_rule[c] + b_fact[c];
    g_lawfinal[w] = s;
    out[w] = s;
  }
}

// ---------------- launch 5: head2 (argmax + lawlang gather), one block ----------------
__global__ void __launch_bounds__(256) head2_kernel(float* __restrict__ out){
  __shared__ int no_s[2];
  int tid = threadIdx.x, wid = tid >> 5, lane = tid & 31;
  if (wid < 2){
    int f = wid;
    float bv = -3.4e38f; int bi = 0;
    for (int c=lane; c<LC; c+=32){
      float v = g_lawfinal[f*LC + c];
      if (v > bv){ bv = v; bi = c; }
    }
    #pragma unroll
    for (int o=16;o>0;o>>=1){
      float ov = __shfl_xor_sync(0xffffffffu, bv, o);
      int   oi = __shfl_xor_sync(0xffffffffu, bi, o);
      if (ov > bv || (ov == bv && oi < bi)){ bv = ov; bi = oi; }
    }
    if (!lane){
      no_s[f] = bi;
      out[672 + f] = (float)bi;
    }
  }
  __syncthreads();
  for (int i=tid; i<2*LC; i+=256){
    int f = i/LC, c = i%LC;
    out[466 + i] = g_lawlang[no_s[f]*LC + c];
  }
}

// ---------------- launch ----------------
extern "C" void kernel_launch(void* const* d_in, const int* in_sizes, int n_in,
                              void* d_out, int out_size){
  const float* output     = (const float*)d_in[0];
  const float* fact_emb   = (const float*)d_in[1];
  const float* law_embs   = (const float*)d_in[2];
  const float* law_masks  = (const float*)d_in[3];
  const float* laws_table = (const float*)d_in[4];
  const float* Wq  = (const float*)d_in[5];
  const float* bq  = (const float*)d_in[6];
  const float* Wk  = (const float*)d_in[7];
  // d_in[8] = bk : softmax-invariant, drops out
  const float* Wv  = (const float*)d_in[9];
  const float* bv  = (const float*)d_in[10];
  const float* w_dprob   = (const float*)d_in[11];
  const float* b_dprob   = (const float*)d_in[12];
  const float* w_lawprob = (const float*)d_in[13];
  const float* b_lawprob = (const float*)d_in[14];
  const float* W_rulelaw = (const float*)d_in[15];
  const float* b_rulelaw = (const float*)d_in[16];
  const float* W_factlaw = (const float*)d_in[17];
  const float* b_factlaw = (const float*)d_in[18];
  const float* W_law = (const float*)d_in[19];
  const float* b_law = (const float*)d_in[20];
  const float* W_accu = (const float*)d_in[21];
  const float* b_accu = (const float*)d_in[22];
  const float* W_term = (const float*)d_in[23];
  const float* b_term = (const float*)d_in[24];
  float* out = (float*)d_out;

  cudaFuncSetAttribute(attn_mma_kernel, cudaFuncAttributeMaxDynamicSharedMemorySize, ATTN_SMEM);
  cudaFuncSetAttribute(k2_t_v1y, cudaFuncAttributeMaxDynamicSharedMemorySize, GEMM_SMEM);

  k1_prep<<<K1_MT + K1_PREP + CONV_BLK + K1_DOTS + K1_LL, 256>>>(
      Wq, Wk, fact_emb, bq, Wv, w_dprob, bv,
      output, laws_table, W_law, b_law, W_accu, b_accu, W_term, b_term, out);
  k2_t_v1y<<<48 + 6592, 256, GEMM_SMEM>>>(law_embs);
  attn_mma_kernel<<<dim3(NFS/128, LC), 256, ATTN_SMEM>>>(law_masks, b_dprob, w_lawprob);
  head1_kernel<<<26,256>>>(b_lawprob, W_rulelaw, b_rulelaw, W_factlaw, b_factlaw, out);
  head2_kernel<<<1,256>>>(out);
}